// round 3
// baseline (speedup 1.0000x reference)
#include <cuda_runtime.h>
#include <cuda_bf16.h>
#include <math.h>

// Problem constants
#define BATCH   32
#define C_COMB  448
#define HW_IN   32          // 32x32 input spatial
#define P_IN    1024        // 32*32
#define HW_FEAT 64
#define N_POS   4096        // 64*64
#define D_PROJ  100
#define OUT_HW  256

// Scratch (device globals; no allocation allowed)
__device__ float g_Wt[C_COMB * D_PROJ];          // [448,100]  W^T
__device__ float g_meanT[N_POS * D_PROJ];        // [4096,100] mean^T
__device__ float g_P[BATCH * P_IN * D_PROJ];     // [32,1024,100] projected feats @32x32
__device__ float g_dist[BATCH * N_POS];          // [32,4096] raw Mahalanobis

// ---------------------------------------------------------------------------
// Kernel 0a: transpose proj_w [100,448] -> g_Wt [448,100]
__global__ void transpose_w_kernel(const float* __restrict__ proj_w) {
    int i = blockIdx.x * 256 + threadIdx.x;
    if (i < C_COMB * D_PROJ) {
        int c = i / D_PROJ, d = i % D_PROJ;
        g_Wt[i] = proj_w[d * C_COMB + c];
    }
}

// Kernel 0b: transpose mean [100,4096] -> g_meanT [4096,100]
__global__ void transpose_mean_kernel(const float* __restrict__ mean) {
    int i = blockIdx.x * 256 + threadIdx.x;
    if (i < N_POS * D_PROJ) {
        int n = i / D_PROJ, d = i % D_PROJ;
        g_meanT[i] = mean[d * N_POS + n];
    }
}

// ---------------------------------------------------------------------------
// Kernel 1: projection GEMM at 32x32 resolution (interp/proj commute).
// P[b, p, d] = sum_c combined[b, c, p] * Wt[c, d] + proj_b[d]
// Block: 128 positions x 100(112 padded) d, K=448, 256 threads, 8x7 thread tile.
__global__ void __launch_bounds__(256) proj_kernel(
    const float* __restrict__ combined,
    const float* __restrict__ proj_b)
{
    const int b  = blockIdx.y;
    const int p0 = blockIdx.x * 128;
    const int tid = threadIdx.x;
    const int tx = tid & 15;   // d dimension
    const int ty = tid >> 4;   // p dimension

    __shared__ float Xs[16][128];
    __shared__ float Ws[16][112];

    float acc[8][7];
#pragma unroll
    for (int i = 0; i < 8; i++)
#pragma unroll
        for (int j = 0; j < 7; j++) acc[i][j] = 0.f;

    const float* Xg = combined + (size_t)b * C_COMB * P_IN + p0;

    for (int c0 = 0; c0 < C_COMB; c0 += 16) {
        // load X tile: 16 rows x 128 contiguous floats
#pragma unroll
        for (int i = tid; i < 16 * 128; i += 256) {
            int kk = i >> 7, pp = i & 127;
            Xs[kk][pp] = Xg[(size_t)(c0 + kk) * P_IN + pp];
        }
        // load W tile (padded to 112 with zeros)
#pragma unroll
        for (int i = tid; i < 16 * 112; i += 256) {
            int kk = i / 112, dd = i % 112;
            Ws[kk][dd] = (dd < D_PROJ) ? g_Wt[(c0 + kk) * D_PROJ + dd] : 0.f;
        }
        __syncthreads();

#pragma unroll
        for (int k = 0; k < 16; k++) {
            float a[8], w[7];
#pragma unroll
            for (int i = 0; i < 8; i++) a[i] = Xs[k][ty + 16 * i];
#pragma unroll
            for (int j = 0; j < 7; j++) w[j] = Ws[k][tx + 16 * j];
#pragma unroll
            for (int i = 0; i < 8; i++)
#pragma unroll
                for (int j = 0; j < 7; j++) acc[i][j] += a[i] * w[j];
        }
        __syncthreads();
    }

#pragma unroll
    for (int i = 0; i < 8; i++) {
        int p = p0 + ty + 16 * i;
#pragma unroll
        for (int j = 0; j < 7; j++) {
            int d = tx + 16 * j;
            if (d < D_PROJ)
                g_P[(size_t)b * (P_IN * D_PROJ) + (size_t)p * D_PROJ + d] =
                    acc[i][j] + proj_b[d];
        }
    }
}

// ---------------------------------------------------------------------------
// Kernel 2: per-position Mahalanobis. One block per n (4096 blocks).
// diff[b,d] = bilinear32->64(P[b,:,d]) - meanT[n,d]
// dist[b]   = diff^T Sigma_n diff
// smem: Sigma[100*100] + diffT[100*36] + dist[32] = 54528 B (dynamic)
#define DIFF_PITCH 36
#define MAHA_SMEM ((D_PROJ*D_PROJ + D_PROJ*DIFF_PITCH + 32) * 4)

__global__ void __launch_bounds__(256) maha_kernel(
    const float* __restrict__ inv_cov)
{
    extern __shared__ float smem[];
    float* Sg  = smem;                                  // [100][100]
    float* dT  = smem + D_PROJ * D_PROJ;                // [100][36] diffT[d][b]
    float* ds  = dT + D_PROJ * DIFF_PITCH;              // [32]

    const int n   = blockIdx.x;
    const int tid = threadIdx.x;

    // ---- load Sigma_n (coalesced from HBM, 40 KB) ----
    const float* Sgl = inv_cov + (size_t)n * (D_PROJ * D_PROJ);
#pragma unroll 4
    for (int i = tid; i < D_PROJ * D_PROJ; i += 256) Sg[i] = Sgl[i];

    // ---- bilinear corner setup (half-pixel, 32->64) ----
    const int Y = n >> 6, X = n & 63;
    float sy = 0.5f * (float)Y - 0.25f;
    float sx = 0.5f * (float)X - 0.25f;
    float fy = floorf(sy), fx = floorf(sx);
    int y0 = max(0, (int)fy), y1 = min(HW_IN - 1, (int)fy + 1);
    int x0 = max(0, (int)fx), x1 = min(HW_IN - 1, (int)fx + 1);
    float wy1 = sy - fy, wy0 = 1.f - wy1;
    float wx1 = sx - fx, wx0 = 1.f - wx1;
    float w00 = wy0 * wx0, w01 = wy0 * wx1, w10 = wy1 * wx0, w11 = wy1 * wx1;
    int p00 = (y0 * HW_IN + x0) * D_PROJ, p01 = (y0 * HW_IN + x1) * D_PROJ;
    int p10 = (y1 * HW_IN + x0) * D_PROJ, p11 = (y1 * HW_IN + x1) * D_PROJ;

    // ---- compute diff (gathers hit L2: g_P is 13 MB, fully resident) ----
    const float* mT = g_meanT + (size_t)n * D_PROJ;
#pragma unroll 2
    for (int i = tid; i < BATCH * D_PROJ; i += 256) {
        int b = i / D_PROJ, d = i % D_PROJ;
        const float* Pb = g_P + (size_t)b * (P_IN * D_PROJ) + d;
        float v = w00 * Pb[p00] + w01 * Pb[p01] + w10 * Pb[p10] + w11 * Pb[p11];
        dT[d * DIFF_PITCH + b] = v - mT[d];
    }
    if (tid < BATCH) ds[tid] = 0.f;
    __syncthreads();

    // ---- T = Diff @ Sigma with 4x4 register tiles; 200 active threads ----
    if (tid < 200) {
        const int bi = tid & 7;         // 8 batch groups
        const int di = tid >> 3;        // 25 d groups
        const int b4 = bi * 4, d4 = di * 4;

        float acc[4][4];
#pragma unroll
        for (int j = 0; j < 4; j++)
#pragma unroll
            for (int k = 0; k < 4; k++) acc[j][k] = 0.f;

#pragma unroll 2
        for (int c = 0; c < D_PROJ; c++) {
            float4 a = *(const float4*)&dT[c * DIFF_PITCH + b4];
            float4 w = *(const float4*)&Sg[c * D_PROJ + d4];
            acc[0][0] += a.x * w.x; acc[0][1] += a.x * w.y;
            acc[0][2] += a.x * w.z; acc[0][3] += a.x * w.w;
            acc[1][0] += a.y * w.x; acc[1][1] += a.y * w.y;
            acc[1][2] += a.y * w.z; acc[1][3] += a.y * w.w;
            acc[2][0] += a.z * w.x; acc[2][1] += a.z * w.y;
            acc[2][2] += a.z * w.z; acc[2][3] += a.z * w.w;
            acc[3][0] += a.w * w.x; acc[3][1] += a.w * w.y;
            acc[3][2] += a.w * w.z; acc[3][3] += a.w * w.w;
        }

        // dist partial: sum_k T[b,d4+k] * diff[b,d4+k]
#pragma unroll
        for (int j = 0; j < 4; j++) {
            float p = acc[j][0] * dT[(d4 + 0) * DIFF_PITCH + b4 + j]
                    + acc[j][1] * dT[(d4 + 1) * DIFF_PITCH + b4 + j]
                    + acc[j][2] * dT[(d4 + 2) * DIFF_PITCH + b4 + j]
                    + acc[j][3] * dT[(d4 + 3) * DIFF_PITCH + b4 + j];
            atomicAdd(&ds[b4 + j], p);
        }
    }
    __syncthreads();

    if (tid < BATCH) g_dist[(size_t)tid * N_POS + n] = ds[tid];
}

// ---------------------------------------------------------------------------
// Kernel 3: normalize + bilinear 64->256 upsample (both linear, commute).
__global__ void __launch_bounds__(256) upsample_kernel(
    const float* __restrict__ nmin_p,
    const float* __restrict__ nmax_p,
    float* __restrict__ out)
{
    const int b = blockIdx.y;
    const int i = blockIdx.x * 256 + threadIdx.x;   // over 256*256
    const int Y = i >> 8, X = i & 255;

    float sy = 0.25f * (float)Y - 0.375f;
    float sx = 0.25f * (float)X - 0.375f;
    float fy = floorf(sy), fx = floorf(sx);
    int y0 = max(0, (int)fy), y1 = min(HW_FEAT - 1, (int)fy + 1);
    int x0 = max(0, (int)fx), x1 = min(HW_FEAT - 1, (int)fx + 1);
    float wy1 = sy - fy, wy0 = 1.f - wy1;
    float wx1 = sx - fx, wx0 = 1.f - wx1;

    const float* D = g_dist + (size_t)b * N_POS;
    float v = wy0 * (wx0 * D[y0 * HW_FEAT + x0] + wx1 * D[y0 * HW_FEAT + x1])
            + wy1 * (wx0 * D[y1 * HW_FEAT + x0] + wx1 * D[y1 * HW_FEAT + x1]);

    float nmin = *nmin_p, nmax = *nmax_p;
    out[(size_t)b * (OUT_HW * OUT_HW) + i] = (v - nmin) / (nmax - nmin + 1e-8f);
}

// ---------------------------------------------------------------------------
extern "C" void kernel_launch(void* const* d_in, const int* in_sizes, int n_in,
                              void* d_out, int out_size)
{
    const float* combined = (const float*)d_in[0];
    const float* proj_w   = (const float*)d_in[1];
    const float* proj_b   = (const float*)d_in[2];
    const float* mean     = (const float*)d_in[3];
    const float* inv_cov  = (const float*)d_in[4];
    const float* nmin     = (const float*)d_in[5];
    const float* nmax     = (const float*)d_in[6];
    float* out            = (float*)d_out;

    cudaFuncSetAttribute(maha_kernel,
                         cudaFuncAttributeMaxDynamicSharedMemorySize, MAHA_SMEM);

    transpose_w_kernel<<<(C_COMB * D_PROJ + 255) / 256, 256>>>(proj_w);
    transpose_mean_kernel<<<(N_POS * D_PROJ + 255) / 256, 256>>>(mean);
    proj_kernel<<<dim3(8, BATCH), 256>>>(combined, proj_b);
    maha_kernel<<<N_POS, 256, MAHA_SMEM>>>(inv_cov);
    upsample_kernel<<<dim3(OUT_HW * OUT_HW / 256, BATCH), 256>>>(nmin, nmax, out);
}